// round 14
// baseline (speedup 1.0000x reference)
#include <cuda_runtime.h>
#include <cuda_bf16.h>
#include <cuda_fp16.h>
#include <cstdint>

#define NN   50000
#define NE   800000
#define NET  850000     // NE + NN self loops
#define NG   256
#define HID  128
#define HEADS 4
#define FULLM 0xffffffffu
#define WSTRIDE 136      // padded smem row stride (bf16 elems) -> conflict-free
#define NBLK_SCAN ((NN + 1023) / 1024)   // 49

// ---------------- device scratch (no allocs allowed) ----------------
__device__ __half g_hh[NN*HID];         // post-GEMM features (fp16, for gather)
__device__ float g_x1[NN*HID];          // final layer output (fp32, for pool)
__device__ __nv_bfloat16 g_xh[NN*HID];  // layer input, bf16 hi
__device__ __nv_bfloat16 g_xl[NN*HID];  // layer input, bf16 lo
__device__ __nv_bfloat16 g_wth[3*HID*HID];  // W^T bf16 hi  [layer][n][k]
__device__ __nv_bfloat16 g_wtl[3*HID*HID];  // W^T bf16 lo
__device__ float g_as[NN*HEADS];
__device__ float g_ad[NN*HEADS];
__device__ int   g_deg[NN];
__device__ int   g_rowptr[NN+1];
__device__ int   g_pos[NN];
__device__ int   g_esrc[NET];
__device__ int   g_bsum[NBLK_SCAN];
__device__ int   g_boff[NBLK_SCAN];

// ---------------- helpers ----------------
__device__ __forceinline__ float lrelu(float v){ return v < 0.f ? 0.2f * v : v; }

__device__ __forceinline__ void mma16816(float* c, uint32_t a0, uint32_t a1, uint32_t a2, uint32_t a3,
                                         uint32_t b0, uint32_t b1){
    asm volatile("mma.sync.aligned.m16n8k16.row.col.f32.bf16.bf16.f32 "
        "{%0,%1,%2,%3}, {%4,%5,%6,%7}, {%8,%9}, {%0,%1,%2,%3};"
        : "+f"(c[0]), "+f"(c[1]), "+f"(c[2]), "+f"(c[3])
        : "r"(a0), "r"(a1), "r"(a2), "r"(a3), "r"(b0), "r"(b1));
}

// split a float2 into packed bf16 hi + lo words
__device__ __forceinline__ uint32_t split_bf16(float2 f, uint32_t& lo){
    __nv_bfloat16 h0 = __float2bfloat16(f.x), h1 = __float2bfloat16(f.y);
    __nv_bfloat162 H = __halves2bfloat162(h0, h1);
    __nv_bfloat162 L = __halves2bfloat162(__float2bfloat16(f.x - __bfloat162float(h0)),
                                          __float2bfloat16(f.y - __bfloat162float(h1)));
    lo = *(uint32_t*)&L;
    return *(uint32_t*)&H;
}

// ---------------- graph build ----------------
__global__ void zero_kernel(){
    int i = blockIdx.x * blockDim.x + threadIdx.x;
    if (i < NN) g_deg[i] = 0;
}

__global__ void count_deg_kernel(const int* __restrict__ ei){
    int e = blockIdx.x * blockDim.x + threadIdx.x;
    if (e >= NET) return;
    int d = (e < NE) ? ei[NE + e] : (e - NE);
    atomicAdd(&g_deg[d], 1);
}

// per-block inclusive scan of g_deg -> g_rowptr[i+1] (local), block totals -> g_bsum
__global__ void scan1_kernel(){
    __shared__ int warp_sums[32];
    int tid = threadIdx.x, lane = tid & 31, wid = tid >> 5;
    int i = blockIdx.x * 1024 + tid;
    int v = (i < NN) ? g_deg[i] : 0;
    int xs = v;
#pragma unroll
    for (int o = 1; o < 32; o <<= 1){
        int t = __shfl_up_sync(FULLM, xs, o);
        if (lane >= o) xs += t;
    }
    if (lane == 31) warp_sums[wid] = xs;
    __syncthreads();
    if (wid == 0){
        int y = warp_sums[lane];
#pragma unroll
        for (int o = 1; o < 32; o <<= 1){
            int t = __shfl_up_sync(FULLM, y, o);
            if (lane >= o) y += t;
        }
        warp_sums[lane] = y;
    }
    __syncthreads();
    int add = (wid > 0 ? warp_sums[wid-1] : 0);
    if (i < NN) g_rowptr[i+1] = xs + add;
    if (tid == 1023) g_bsum[blockIdx.x] = xs + add;
}

__global__ void scan2_kernel(){
    if (threadIdx.x == 0){
        int run = 0;
        for (int b = 0; b < NBLK_SCAN; b++){ g_boff[b] = run; run += g_bsum[b]; }
    }
}

__global__ void scan3_kernel(){
    int i = blockIdx.x * blockDim.x + threadIdx.x;
    if (i == 0) g_rowptr[0] = 0;
    if (i < NN){
        int r = g_rowptr[i+1] + g_boff[i >> 10];
        g_rowptr[i+1] = r;
        g_pos[i] = r - g_deg[i];
    }
}

__global__ void scatter_kernel(const int* __restrict__ ei){
    int e = blockIdx.x * blockDim.x + threadIdx.x;
    if (e >= NET) return;
    int s, d;
    if (e < NE){ s = ei[e]; d = ei[NE + e]; }
    else       { s = e - NE; d = e - NE; }
    int idx = atomicAdd(&g_pos[d], 1);
    g_esrc[idx] = s;
}

// ---------------- W conversion (hi + lo, 3-phase split-bf16) -----------------
__global__ void wconv_kernel(const float* __restrict__ W){
    int t = blockIdx.x * blockDim.x + threadIdx.x;
    if (t >= 3*HID*HID) return;
    int l = t / (HID*HID), r = t - l*(HID*HID);
    int n = r >> 7, k = r & 127;
    float v = W[l*HID*HID + k*HID + n];   // transpose: [l][n][k] = W[l][k][n]
    __nv_bfloat16 h = __float2bfloat16(v);
    g_wth[t] = h;
    g_wtl[t] = __float2bfloat16(v - __bfloat162float(h));
}

// ---------------- tensor-core GEMM h = x*W (+ fused alpha projections) --------
// CTA = 256 thr = 8 warps as 4 Mgroups x 2 Ngroups. Warp output: M=32 x N=64,
// processed as TWO sequential N=32 halves with a 32-register accumulator so the
// kernel fits 3 CTAs/SM (__launch_bounds__(256,3), <=85 regs) for latency hiding.
// 3-phase split-bf16: Ah*Bh + Al*Bh + Ah*Bl (proven 2.7e-5 logits error).
__global__ void __launch_bounds__(256, 3) gemm_mma_kernel(int layer, int srcF32,
        const float* __restrict__ xin,
        const float* __restrict__ attS, const float* __restrict__ attD){
    extern __shared__ __nv_bfloat16 ws[];          // [2][128][WSTRIDE]
    __nv_bfloat16* wh_s = ws;
    __nv_bfloat16* wl_s = ws + 128*WSTRIDE;

    int tid = threadIdx.x, lane = tid & 31, wid = tid >> 5;
    int Mg = wid >> 1, Ng = wid & 1;

    // stage W^T hi/lo into smem (row = n, 128 rows x 128 bf16 each)
    {
        const uint4* src_h = (const uint4*)&g_wth[(size_t)layer*HID*HID];
        const uint4* src_l = (const uint4*)&g_wtl[(size_t)layer*HID*HID];
        for (int i = tid; i < 2048; i += 256){     // 2048 uint4 per matrix
            int row = i >> 4, c16 = i & 15;
            *(uint4*)((char*)wh_s + row*(WSTRIDE*2) + c16*16) = src_h[i];
            *(uint4*)((char*)wl_s + row*(WSTRIDE*2) + c16*16) = src_l[i];
        }
    }
    __syncthreads();

    int rowBase = blockIdx.x * 128 + Mg * 32;
    int rq = lane >> 2;            // 0..7
    int kcol = (lane & 3) * 2;

#pragma unroll 1
    for (int half = 0; half < 2; half++){
        float acc[32];                 // [mt 2][nt 4][frag 4]
#pragma unroll
        for (int i = 0; i < 32; i++) acc[i] = 0.f;

#pragma unroll
        for (int ks = 0; ks < 8; ks++){
            int k0 = ks * 16;
            uint32_t ah[2][4], al[2][4];
#pragma unroll
            for (int mt = 0; mt < 2; mt++){
                int r0 = min(rowBase + mt*16 + rq,     NN-1);
                int r8 = min(rowBase + mt*16 + rq + 8, NN-1);
                if (srcF32){
                    float2 f00 = *(const float2*)&xin[(size_t)r0*HID + k0 + kcol];
                    float2 f10 = *(const float2*)&xin[(size_t)r8*HID + k0 + kcol];
                    float2 f01 = *(const float2*)&xin[(size_t)r0*HID + k0 + kcol + 8];
                    float2 f11 = *(const float2*)&xin[(size_t)r8*HID + k0 + kcol + 8];
                    ah[mt][0] = split_bf16(f00, al[mt][0]);
                    ah[mt][1] = split_bf16(f10, al[mt][1]);
                    ah[mt][2] = split_bf16(f01, al[mt][2]);
                    ah[mt][3] = split_bf16(f11, al[mt][3]);
                } else {
                    ah[mt][0] = *(const uint32_t*)&g_xh[(size_t)r0*HID + k0 + kcol];
                    ah[mt][1] = *(const uint32_t*)&g_xh[(size_t)r8*HID + k0 + kcol];
                    ah[mt][2] = *(const uint32_t*)&g_xh[(size_t)r0*HID + k0 + kcol + 8];
                    ah[mt][3] = *(const uint32_t*)&g_xh[(size_t)r8*HID + k0 + kcol + 8];
                    al[mt][0] = *(const uint32_t*)&g_xl[(size_t)r0*HID + k0 + kcol];
                    al[mt][1] = *(const uint32_t*)&g_xl[(size_t)r8*HID + k0 + kcol];
                    al[mt][2] = *(const uint32_t*)&g_xl[(size_t)r0*HID + k0 + kcol + 8];
                    al[mt][3] = *(const uint32_t*)&g_xl[(size_t)r8*HID + k0 + kcol + 8];
                }
            }
#pragma unroll
            for (int nt = 0; nt < 4; nt++){
                int n = Ng*64 + half*32 + nt*8 + rq;
                uint32_t bh0 = *(const uint32_t*)&wh_s[n*WSTRIDE + k0 + kcol];
                uint32_t bh1 = *(const uint32_t*)&wh_s[n*WSTRIDE + k0 + kcol + 8];
                uint32_t bl0 = *(const uint32_t*)&wl_s[n*WSTRIDE + k0 + kcol];
                uint32_t bl1 = *(const uint32_t*)&wl_s[n*WSTRIDE + k0 + kcol + 8];
#pragma unroll
                for (int mt = 0; mt < 2; mt++){
                    float* a = &acc[(mt*4 + nt)*4];
                    mma16816(a, ah[mt][0], ah[mt][1], ah[mt][2], ah[mt][3], bh0, bh1);
                    mma16816(a, al[mt][0], al[mt][1], al[mt][2], al[mt][3], bh0, bh1);
                    mma16816(a, ah[mt][0], ah[mt][1], ah[mt][2], ah[mt][3], bl0, bl1);
                }
            }
        }

        // epilogue for this half: cols [Ng*64 + half*32, +32) = head Ng*2 + half
        int head = Ng*2 + half;
#pragma unroll
        for (int mt = 0; mt < 2; mt++){
            int r0 = rowBase + mt*16 + rq;
            int r1 = r0 + 8;
            float s0 = 0.f, d0 = 0.f, s1 = 0.f, d1 = 0.f;
#pragma unroll
            for (int nt = 0; nt < 4; nt++){
                int c = Ng*64 + half*32 + nt*8 + (lane & 3)*2;
                float aS0 = __ldg(&attS[c]), aS1 = __ldg(&attS[c+1]);
                float aD0 = __ldg(&attD[c]), aD1 = __ldg(&attD[c+1]);
                float* a = &acc[(mt*4 + nt)*4];
                s0 += a[0]*aS0 + a[1]*aS1;  d0 += a[0]*aD0 + a[1]*aD1;
                s1 += a[2]*aS0 + a[3]*aS1;  d1 += a[2]*aD0 + a[3]*aD1;
                if (r0 < NN) *(__half2*)&g_hh[(size_t)r0*HID + c] = __floats2half2_rn(a[0], a[1]);
                if (r1 < NN) *(__half2*)&g_hh[(size_t)r1*HID + c] = __floats2half2_rn(a[2], a[3]);
            }
            s0 += __shfl_xor_sync(FULLM, s0, 1); s0 += __shfl_xor_sync(FULLM, s0, 2);
            d0 += __shfl_xor_sync(FULLM, d0, 1); d0 += __shfl_xor_sync(FULLM, d0, 2);
            s1 += __shfl_xor_sync(FULLM, s1, 1); s1 += __shfl_xor_sync(FULLM, s1, 2);
            d1 += __shfl_xor_sync(FULLM, d1, 1); d1 += __shfl_xor_sync(FULLM, d1, 2);
            if ((lane & 3) == 0){
                if (r0 < NN){ g_as[r0*4 + head] = s0; g_ad[r0*4 + head] = d0; }
                if (r1 < NN){ g_as[r1*4 + head] = s1; g_ad[r1*4 + head] = d1; }
            }
        }
    }
}

// ---------------- fused single-pass softmax-aggregation + bias/BN/ELU --------
// warp per dst node (round-8 proven variant). Chunks of 8 edges:
//   lane l preloads exp score for (edge base+(l&7), head l>>3) -> exp once per (edge,head);
//   inner loop per edge: 2 shfl + 1 LDG.64 + FFMAs.
// Store elision: final layer (writeF32=1) writes only g_x1; earlier layers only g_xh/g_xl.
__global__ void agg_kernel(const float* __restrict__ bias,
                           const float* __restrict__ gam,
                           const float* __restrict__ bet,
                           const float* __restrict__ mea,
                           const float* __restrict__ var,
                           int writeF32){
    int v = blockIdx.x * 8 + (threadIdx.x >> 5);
    if (v >= NN) return;
    int lane = threadIdx.x & 31;
    int head = lane >> 3;
    int esub = lane & 7;
    int srcBase = head << 3;          // lane & 24

    float adh = g_ad[v*4 + head];
    int begin = g_rowptr[v], end = g_rowptr[v+1];

    float4 acc = {0,0,0,0};
    float denom = 0.f;

    for (int base = begin; base < end; base += 8){
        int n = end - base; if (n > 8) n = 8;
        int eidx = base + esub; if (eidx >= end) eidx = end - 1;
        int sidx = g_esrc[eidx];
        float e = __expf(lrelu(__ldg(&g_as[sidx*4 + head]) + adh));
#pragma unroll
        for (int j = 0; j < 8; j++){
            if (j >= n) break;
            int s = __shfl_sync(FULLM, sidx, j);
            float ej = __shfl_sync(FULLM, e, srcBase + j);
            uint2 p = *(const uint2*)&g_hh[(size_t)s*HID + lane*4];
            float2 fa = __half22float2(*reinterpret_cast<__half2*>(&p.x));
            float2 fb = __half22float2(*reinterpret_cast<__half2*>(&p.y));
            denom += ej;
            acc.x += ej*fa.x; acc.y += ej*fa.y;
            acc.z += ej*fb.x; acc.w += ej*fb.y;
        }
    }
    float inv = 1.0f / denom;
    acc.x *= inv; acc.y *= inv; acc.z *= inv; acc.w *= inv;

    // epilogue: bias + BN + ELU
    int c = lane * 4;
    float4 bi = *(const float4*)&bias[c];
    float4 gg = *(const float4*)&gam[c];
    float4 bb = *(const float4*)&bet[c];
    float4 mm = *(const float4*)&mea[c];
    float4 vv = *(const float4*)&var[c];
    float4 r;
    r.x = (acc.x + bi.x - mm.x) * (gg.x * rsqrtf(vv.x + 1e-5f)) + bb.x;
    r.y = (acc.y + bi.y - mm.y) * (gg.y * rsqrtf(vv.y + 1e-5f)) + bb.y;
    r.z = (acc.z + bi.z - mm.z) * (gg.z * rsqrtf(vv.z + 1e-5f)) + bb.z;
    r.w = (acc.w + bi.w - mm.w) * (gg.w * rsqrtf(vv.w + 1e-5f)) + bb.w;
    r.x = r.x > 0.f ? r.x : (expf(r.x) - 1.f);
    r.y = r.y > 0.f ? r.y : (expf(r.y) - 1.f);
    r.z = r.z > 0.f ? r.z : (expf(r.z) - 1.f);
    r.w = r.w > 0.f ? r.w : (expf(r.w) - 1.f);

    if (writeF32){
        // final layer: only the pooling path consumes this
        *(float4*)&g_x1[(size_t)v*HID + c] = r;
    } else {
        // split-bf16 outputs for next layer's tensor GEMM
        uint32_t l0, l1;
        uint32_t h0w = split_bf16({r.x, r.y}, l0);
        uint32_t h1w = split_bf16({r.z, r.w}, l1);
        uint2 hw = {h0w, h1w}, lw = {l0, l1};
        *(uint2*)&g_xh[(size_t)v*HID + c] = hw;
        *(uint2*)&g_xl[(size_t)v*HID + c] = lw;
    }
}

// ---------------- fused pool + head (batch is sorted by graph) ---------------
__global__ void pool_head_kernel(const int* __restrict__ batch,
                                 const float* __restrict__ f1w, const float* __restrict__ f1b,
                                 const float* __restrict__ f2w, const float* __restrict__ f2b,
                                 float* __restrict__ out){
    __shared__ float meanv[HID];
    __shared__ float hm[64];
    int g = blockIdx.x, tid = threadIdx.x;   // 128 threads

    int lo = 0, hi = NN;
    while (lo < hi){ int mid = (lo + hi) >> 1; if (batch[mid] < g) lo = mid + 1; else hi = mid; }
    int start = lo;
    hi = NN;
    while (lo < hi){ int mid = (lo + hi) >> 1; if (batch[mid] < g + 1) lo = mid + 1; else hi = mid; }
    int end = lo;

    float s = 0.f;
    for (int n = start; n < end; n++) s += g_x1[(size_t)n*HID + tid];
    float cnt = fmaxf((float)(end - start), 1.0f);
    meanv[tid] = s / cnt;
    __syncthreads();
    if (tid < 64){
        float a = f1b[tid];
#pragma unroll 8
        for (int k = 0; k < HID; k++) a += meanv[k] * f1w[k*64 + tid];
        hm[tid] = fmaxf(a, 0.f);
    }
    __syncthreads();
    if (tid < 10){
        float o = f2b[tid];
#pragma unroll 8
        for (int k = 0; k < 64; k++) o += hm[k] * f2w[k*10 + tid];
        out[g*10 + tid] = o;
    }
}

// ---------------- launch ----------------
extern "C" void kernel_launch(void* const* d_in, const int* in_sizes, int n_in,
                              void* d_out, int out_size){
    const float* x     = (const float*)d_in[0];
    const int*   ei    = (const int*)d_in[1];
    const int*   batch = (const int*)d_in[2];
    const float* W    = (const float*)d_in[3];
    const float* attS = (const float*)d_in[4];
    const float* attD = (const float*)d_in[5];
    const float* bias = (const float*)d_in[6];
    const float* gam  = (const float*)d_in[7];
    const float* bet  = (const float*)d_in[8];
    const float* mea  = (const float*)d_in[9];
    const float* var  = (const float*)d_in[10];
    const float* f1w  = (const float*)d_in[11];
    const float* f1b  = (const float*)d_in[12];
    const float* f2w  = (const float*)d_in[13];
    const float* f2b  = (const float*)d_in[14];
    float* out = (float*)d_out;

    const int smem_bytes = 2 * 128 * WSTRIDE * 2;   // 69632
    cudaFuncSetAttribute(gemm_mma_kernel, cudaFuncAttributeMaxDynamicSharedMemorySize, smem_bytes);

    const int gemm_blocks = (NN + 127) / 128;   // 391
    const int agg_blocks  = (NN + 7) / 8;

    wconv_kernel    <<<(3*HID*HID + 255)/256, 256>>>(W);
    zero_kernel     <<<(NN + 255)/256, 256>>>();
    count_deg_kernel<<<(NET + 255)/256, 256>>>(ei);
    gemm_mma_kernel <<<gemm_blocks, 256, smem_bytes>>>(0, 1, x, attS,             attD);   // capture slot
    scan1_kernel    <<<NBLK_SCAN, 1024>>>();
    scan2_kernel    <<<1, 32>>>();
    scan3_kernel    <<<(NN + 255)/256, 256>>>();
    scatter_kernel  <<<(NET + 255)/256, 256>>>(ei);
    agg_kernel      <<<agg_blocks, 256>>>(bias,         gam,         bet,         mea,         var,         0);
    gemm_mma_kernel <<<gemm_blocks, 256, smem_bytes>>>(1, 0, x, attS + HEADS*32,  attD + HEADS*32);
    agg_kernel      <<<agg_blocks, 256>>>(bias + HID,   gam + HID,   bet + HID,   mea + HID,   var + HID,   0);
    gemm_mma_kernel <<<gemm_blocks, 256, smem_bytes>>>(2, 0, x, attS + 2*HEADS*32, attD + 2*HEADS*32);
    agg_kernel      <<<agg_blocks, 256>>>(bias + 2*HID, gam + 2*HID, bet + 2*HID, mea + 2*HID, var + 2*HID, 1);

    pool_head_kernel<<<NG, 128>>>(batch, f1w, f1b, f2w, f2b, out);
}

// round 15
// speedup vs baseline: 1.5903x; 1.5903x over previous
#include <cuda_runtime.h>
#include <cuda_bf16.h>
#include <cuda_fp16.h>
#include <cstdint>

#define NN   50000
#define NE   800000
#define NET  850000     // NE + NN self loops
#define NG   256
#define HID  128
#define HEADS 4
#define FULLM 0xffffffffu
#define WSTRIDE 136      // padded smem row stride (bf16 elems) -> conflict-free
#define NBLK_SCAN ((NN + 1023) / 1024)   // 49

// ---------------- device scratch (no allocs allowed) ----------------
__device__ __half g_hh[NN*HID];         // post-GEMM features (fp16, for gather)
__device__ float g_x1[NN*HID];          // final layer output (fp32, for pool)
__device__ __nv_bfloat16 g_xh[NN*HID];  // layer input, bf16 hi
__device__ __nv_bfloat16 g_xl[NN*HID];  // layer input, bf16 lo
__device__ __nv_bfloat16 g_wth[3*HID*HID];  // W^T bf16 hi  [layer][n][k]
__device__ __nv_bfloat16 g_wtl[3*HID*HID];  // W^T bf16 lo
__device__ float g_as[NN*HEADS];
__device__ float g_ad[NN*HEADS];
__device__ int   g_deg[NN];
__device__ int   g_rowptr[NN+1];
__device__ int   g_pos[NN];
__device__ int   g_esrc[NET];
__device__ int   g_bsum[NBLK_SCAN];

// ---------------- helpers ----------------
__device__ __forceinline__ float lrelu(float v){ return v < 0.f ? 0.2f * v : v; }

__device__ __forceinline__ void mma16816(float* c, uint32_t a0, uint32_t a1, uint32_t a2, uint32_t a3,
                                         uint32_t b0, uint32_t b1){
    asm volatile("mma.sync.aligned.m16n8k16.row.col.f32.bf16.bf16.f32 "
        "{%0,%1,%2,%3}, {%4,%5,%6,%7}, {%8,%9}, {%0,%1,%2,%3};"
        : "+f"(c[0]), "+f"(c[1]), "+f"(c[2]), "+f"(c[3])
        : "r"(a0), "r"(a1), "r"(a2), "r"(a3), "r"(b0), "r"(b1));
}

// split a float2 into packed bf16 hi + lo words
__device__ __forceinline__ uint32_t split_bf16(float2 f, uint32_t& lo){
    __nv_bfloat16 h0 = __float2bfloat16(f.x), h1 = __float2bfloat16(f.y);
    __nv_bfloat162 H = __halves2bfloat162(h0, h1);
    __nv_bfloat162 L = __halves2bfloat162(__float2bfloat16(f.x - __bfloat162float(h0)),
                                          __float2bfloat16(f.y - __bfloat162float(h1)));
    lo = *(uint32_t*)&L;
    return *(uint32_t*)&H;
}

// ---------------- graph build + W conversion -------------------------------
// fused: zero g_deg (i < NN) and transpose/split W (i < 3*HID*HID)
__global__ void wconv_zero_kernel(const float* __restrict__ W){
    int t = blockIdx.x * blockDim.x + threadIdx.x;
    if (t < NN) g_deg[t] = 0;
    if (t < 3*HID*HID){
        int l = t / (HID*HID), r = t - l*(HID*HID);
        int n = r >> 7, k = r & 127;
        float v = W[l*HID*HID + k*HID + n];   // transpose: [l][n][k] = W[l][k][n]
        __nv_bfloat16 h = __float2bfloat16(v);
        g_wth[t] = h;
        g_wtl[t] = __float2bfloat16(v - __bfloat162float(h));
    }
}

__global__ void count_deg_kernel(const int* __restrict__ ei){
    int e = blockIdx.x * blockDim.x + threadIdx.x;
    if (e >= NET) return;
    int d = (e < NE) ? ei[NE + e] : (e - NE);
    atomicAdd(&g_deg[d], 1);
}

// per-block inclusive scan of g_deg -> g_rowptr[i+1] (local), block totals -> g_bsum
__global__ void scan1_kernel(){
    __shared__ int warp_sums[32];
    int tid = threadIdx.x, lane = tid & 31, wid = tid >> 5;
    int i = blockIdx.x * 1024 + tid;
    int v = (i < NN) ? g_deg[i] : 0;
    int xs = v;
#pragma unroll
    for (int o = 1; o < 32; o <<= 1){
        int t = __shfl_up_sync(FULLM, xs, o);
        if (lane >= o) xs += t;
    }
    if (lane == 31) warp_sums[wid] = xs;
    __syncthreads();
    if (wid == 0){
        int y = warp_sums[lane];
#pragma unroll
        for (int o = 1; o < 32; o <<= 1){
            int t = __shfl_up_sync(FULLM, y, o);
            if (lane >= o) y += t;
        }
        warp_sums[lane] = y;
    }
    __syncthreads();
    int add = (wid > 0 ? warp_sums[wid-1] : 0);
    if (i < NN) g_rowptr[i+1] = xs + add;
    if (tid == 1023) g_bsum[blockIdx.x] = xs + add;
}

// adds block-prefix (computed redundantly per block: <=49 independent loads)
// and emits final rowptr + scatter cursor. 256 | 1024 so each block spans
// exactly one scan-block (sb = blockIdx.x >> 2).
__global__ void scan3_kernel(){
    __shared__ int carry_s;
    if (threadIdx.x == 0){
        int sb = blockIdx.x >> 2;
        int run = 0;
        for (int b = 0; b < sb; b++) run += g_bsum[b];
        carry_s = run;
    }
    __syncthreads();
    int carry = carry_s;
    int i = blockIdx.x * blockDim.x + threadIdx.x;
    if (i == 0) g_rowptr[0] = 0;
    if (i < NN){
        int r = g_rowptr[i+1] + carry;
        g_rowptr[i+1] = r;
        g_pos[i] = r - g_deg[i];
    }
}

__global__ void scatter_kernel(const int* __restrict__ ei){
    int e = blockIdx.x * blockDim.x + threadIdx.x;
    if (e >= NET) return;
    int s, d;
    if (e < NE){ s = ei[e]; d = ei[NE + e]; }
    else       { s = e - NE; d = e - NE; }
    int idx = atomicAdd(&g_pos[d], 1);
    g_esrc[idx] = s;
}

// ---------------- tensor-core GEMM h = x*W (+ fused alpha projections) --------
// CTA = 256 thr = 8 warps as 4 Mgroups x 2 Ngroups. Warp tile: M=32 (2 mtiles), N=64 (8 nt).
// 3-phase split-bf16: Ah*Bh + Al*Bh + Ah*Bl (proven 2.7e-5 logits error).
__global__ void __launch_bounds__(256, 2) gemm_mma_kernel(int layer, int srcF32,
        const float* __restrict__ xin,
        const float* __restrict__ attS, const float* __restrict__ attD){
    extern __shared__ __nv_bfloat16 ws[];          // [2][128][WSTRIDE]
    __nv_bfloat16* wh_s = ws;
    __nv_bfloat16* wl_s = ws + 128*WSTRIDE;

    int tid = threadIdx.x, lane = tid & 31, wid = tid >> 5;
    int Mg = wid >> 1, Ng = wid & 1;

    // stage W^T hi/lo into smem (row = n, 128 rows x 128 bf16 each)
    {
        const uint4* src_h = (const uint4*)&g_wth[(size_t)layer*HID*HID];
        const uint4* src_l = (const uint4*)&g_wtl[(size_t)layer*HID*HID];
        for (int i = tid; i < 2048; i += 256){     // 2048 uint4 per matrix
            int row = i >> 4, c16 = i & 15;
            *(uint4*)((char*)wh_s + row*(WSTRIDE*2) + c16*16) = src_h[i];
            *(uint4*)((char*)wl_s + row*(WSTRIDE*2) + c16*16) = src_l[i];
        }
    }
    __syncthreads();

    int rowBase = blockIdx.x * 128 + Mg * 32;
    int rq = lane >> 2;            // 0..7
    int kcol = (lane & 3) * 2;

    float acc[64];                 // [mt 2][nt 8][frag 4]
#pragma unroll
    for (int i = 0; i < 64; i++) acc[i] = 0.f;

#pragma unroll
    for (int ks = 0; ks < 8; ks++){
        int k0 = ks * 16;
        uint32_t ah[2][4], al[2][4];
#pragma unroll
        for (int mt = 0; mt < 2; mt++){
            int r0 = min(rowBase + mt*16 + rq,     NN-1);
            int r8 = min(rowBase + mt*16 + rq + 8, NN-1);
            if (srcF32){
                float2 f00 = *(const float2*)&xin[(size_t)r0*HID + k0 + kcol];
                float2 f10 = *(const float2*)&xin[(size_t)r8*HID + k0 + kcol];
                float2 f01 = *(const float2*)&xin[(size_t)r0*HID + k0 + kcol + 8];
                float2 f11 = *(const float2*)&xin[(size_t)r8*HID + k0 + kcol + 8];
                ah[mt][0] = split_bf16(f00, al[mt][0]);
                ah[mt][1] = split_bf16(f10, al[mt][1]);
                ah[mt][2] = split_bf16(f01, al[mt][2]);
                ah[mt][3] = split_bf16(f11, al[mt][3]);
            } else {
                ah[mt][0] = *(const uint32_t*)&g_xh[(size_t)r0*HID + k0 + kcol];
                ah[mt][1] = *(const uint32_t*)&g_xh[(size_t)r8*HID + k0 + kcol];
                ah[mt][2] = *(const uint32_t*)&g_xh[(size_t)r0*HID + k0 + kcol + 8];
                ah[mt][3] = *(const uint32_t*)&g_xh[(size_t)r8*HID + k0 + kcol + 8];
                al[mt][0] = *(const uint32_t*)&g_xl[(size_t)r0*HID + k0 + kcol];
                al[mt][1] = *(const uint32_t*)&g_xl[(size_t)r8*HID + k0 + kcol];
                al[mt][2] = *(const uint32_t*)&g_xl[(size_t)r0*HID + k0 + kcol + 8];
                al[mt][3] = *(const uint32_t*)&g_xl[(size_t)r8*HID + k0 + kcol + 8];
            }
        }
#pragma unroll
        for (int nt = 0; nt < 8; nt++){
            int n = Ng*64 + nt*8 + rq;
            uint32_t bh0 = *(const uint32_t*)&wh_s[n*WSTRIDE + k0 + kcol];
            uint32_t bh1 = *(const uint32_t*)&wh_s[n*WSTRIDE + k0 + kcol + 8];
            uint32_t bl0 = *(const uint32_t*)&wl_s[n*WSTRIDE + k0 + kcol];
            uint32_t bl1 = *(const uint32_t*)&wl_s[n*WSTRIDE + k0 + kcol + 8];
#pragma unroll
            for (int mt = 0; mt < 2; mt++){
                float* a = &acc[(mt*8 + nt)*4];
                mma16816(a, ah[mt][0], ah[mt][1], ah[mt][2], ah[mt][3], bh0, bh1);
                mma16816(a, al[mt][0], al[mt][1], al[mt][2], al[mt][3], bh0, bh1);
                mma16816(a, ah[mt][0], ah[mt][1], ah[mt][2], ah[mt][3], bl0, bl1);
            }
        }
    }

    // epilogue: warp owns cols [Ng*64, Ng*64+64) = heads 2Ng and 2Ng+1.
#pragma unroll
    for (int mt = 0; mt < 2; mt++){
        int r0 = rowBase + mt*16 + rq;
        int r1 = r0 + 8;
        float s0[2] = {0,0}, d0[2] = {0,0}, s1[2] = {0,0}, d1[2] = {0,0};
#pragma unroll
        for (int nt = 0; nt < 8; nt++){
            int c = Ng*64 + nt*8 + (lane & 3)*2;
            int hh = nt >> 2;                       // head within warp (0/1)
            float aS0 = __ldg(&attS[c]), aS1 = __ldg(&attS[c+1]);
            float aD0 = __ldg(&attD[c]), aD1 = __ldg(&attD[c+1]);
            float* a = &acc[(mt*8 + nt)*4];
            s0[hh] += a[0]*aS0 + a[1]*aS1;  d0[hh] += a[0]*aD0 + a[1]*aD1;
            s1[hh] += a[2]*aS0 + a[3]*aS1;  d1[hh] += a[2]*aD0 + a[3]*aD1;
            if (r0 < NN) *(__half2*)&g_hh[(size_t)r0*HID + c] = __floats2half2_rn(a[0], a[1]);
            if (r1 < NN) *(__half2*)&g_hh[(size_t)r1*HID + c] = __floats2half2_rn(a[2], a[3]);
        }
#pragma unroll
        for (int hh = 0; hh < 2; hh++){
            s0[hh] += __shfl_xor_sync(FULLM, s0[hh], 1); s0[hh] += __shfl_xor_sync(FULLM, s0[hh], 2);
            d0[hh] += __shfl_xor_sync(FULLM, d0[hh], 1); d0[hh] += __shfl_xor_sync(FULLM, d0[hh], 2);
            s1[hh] += __shfl_xor_sync(FULLM, s1[hh], 1); s1[hh] += __shfl_xor_sync(FULLM, s1[hh], 2);
            d1[hh] += __shfl_xor_sync(FULLM, d1[hh], 1); d1[hh] += __shfl_xor_sync(FULLM, d1[hh], 2);
        }
        if ((lane & 3) == 0){
            if (r0 < NN){
#pragma unroll
                for (int hh = 0; hh < 2; hh++){ g_as[r0*4 + Ng*2 + hh] = s0[hh]; g_ad[r0*4 + Ng*2 + hh] = d0[hh]; }
            }
            if (r1 < NN){
#pragma unroll
                for (int hh = 0; hh < 2; hh++){ g_as[r1*4 + Ng*2 + hh] = s1[hh]; g_ad[r1*4 + Ng*2 + hh] = d1[hh]; }
            }
        }
    }
}

// ---------------- fused single-pass softmax-aggregation + bias/BN/ELU --------
// warp per dst node (round-8 proven variant). Chunks of 8 edges:
//   lane l preloads exp score for (edge base+(l&7), head l>>3) -> exp once per (edge,head);
//   inner loop per edge: 2 shfl + 1 LDG.64 + FFMAs.
// Store elision: final layer (writeF32=1) writes only g_x1; earlier layers only g_xh/g_xl.
__global__ void agg_kernel(const float* __restrict__ bias,
                           const float* __restrict__ gam,
                           const float* __restrict__ bet,
                           const float* __restrict__ mea,
                           const float* __restrict__ var,
                           int writeF32){
    int v = blockIdx.x * 8 + (threadIdx.x >> 5);
    if (v >= NN) return;
    int lane = threadIdx.x & 31;
    int head = lane >> 3;
    int esub = lane & 7;
    int srcBase = head << 3;          // lane & 24

    float adh = g_ad[v*4 + head];
    int begin = g_rowptr[v], end = g_rowptr[v+1];

    float4 acc = {0,0,0,0};
    float denom = 0.f;

    for (int base = begin; base < end; base += 8){
        int n = end - base; if (n > 8) n = 8;
        int eidx = base + esub; if (eidx >= end) eidx = end - 1;
        int sidx = g_esrc[eidx];
        float e = __expf(lrelu(__ldg(&g_as[sidx*4 + head]) + adh));
#pragma unroll
        for (int j = 0; j < 8; j++){
            if (j >= n) break;
            int s = __shfl_sync(FULLM, sidx, j);
            float ej = __shfl_sync(FULLM, e, srcBase + j);
            uint2 p = *(const uint2*)&g_hh[(size_t)s*HID + lane*4];
            float2 fa = __half22float2(*reinterpret_cast<__half2*>(&p.x));
            float2 fb = __half22float2(*reinterpret_cast<__half2*>(&p.y));
            denom += ej;
            acc.x += ej*fa.x; acc.y += ej*fa.y;
            acc.z += ej*fb.x; acc.w += ej*fb.y;
        }
    }
    float inv = 1.0f / denom;
    acc.x *= inv; acc.y *= inv; acc.z *= inv; acc.w *= inv;

    // epilogue: bias + BN + ELU
    int c = lane * 4;
    float4 bi = *(const float4*)&bias[c];
    float4 gg = *(const float4*)&gam[c];
    float4 bb = *(const float4*)&bet[c];
    float4 mm = *(const float4*)&mea[c];
    float4 vv = *(const float4*)&var[c];
    float4 r;
    r.x = (acc.x + bi.x - mm.x) * (gg.x * rsqrtf(vv.x + 1e-5f)) + bb.x;
    r.y = (acc.y + bi.y - mm.y) * (gg.y * rsqrtf(vv.y + 1e-5f)) + bb.y;
    r.z = (acc.z + bi.z - mm.z) * (gg.z * rsqrtf(vv.z + 1e-5f)) + bb.z;
    r.w = (acc.w + bi.w - mm.w) * (gg.w * rsqrtf(vv.w + 1e-5f)) + bb.w;
    r.x = r.x > 0.f ? r.x : (expf(r.x) - 1.f);
    r.y = r.y > 0.f ? r.y : (expf(r.y) - 1.f);
    r.z = r.z > 0.f ? r.z : (expf(r.z) - 1.f);
    r.w = r.w > 0.f ? r.w : (expf(r.w) - 1.f);

    if (writeF32){
        // final layer: only the pooling path consumes this
        *(float4*)&g_x1[(size_t)v*HID + c] = r;
    } else {
        // split-bf16 outputs for next layer's tensor GEMM
        uint32_t l0, l1;
        uint32_t h0w = split_bf16({r.x, r.y}, l0);
        uint32_t h1w = split_bf16({r.z, r.w}, l1);
        uint2 hw = {h0w, h1w}, lw = {l0, l1};
        *(uint2*)&g_xh[(size_t)v*HID + c] = hw;
        *(uint2*)&g_xl[(size_t)v*HID + c] = lw;
    }
}

// ---------------- fused pool + head (batch is sorted by graph) ---------------
__global__ void pool_head_kernel(const int* __restrict__ batch,
                                 const float* __restrict__ f1w, const float* __restrict__ f1b,
                                 const float* __restrict__ f2w, const float* __restrict__ f2b,
                                 float* __restrict__ out){
    __shared__ float meanv[HID];
    __shared__ float hm[64];
    int g = blockIdx.x, tid = threadIdx.x;   // 128 threads

    int lo = 0, hi = NN;
    while (lo < hi){ int mid = (lo + hi) >> 1; if (batch[mid] < g) lo = mid + 1; else hi = mid; }
    int start = lo;
    hi = NN;
    while (lo < hi){ int mid = (lo + hi) >> 1; if (batch[mid] < g + 1) lo = mid + 1; else hi = mid; }
    int end = lo;

    float s = 0.f;
    for (int n = start; n < end; n++) s += g_x1[(size_t)n*HID + tid];
    float cnt = fmaxf((float)(end - start), 1.0f);
    meanv[tid] = s / cnt;
    __syncthreads();
    if (tid < 64){
        float a = f1b[tid];
#pragma unroll 8
        for (int k = 0; k < HID; k++) a += meanv[k] * f1w[k*64 + tid];
        hm[tid] = fmaxf(a, 0.f);
    }
    __syncthreads();
    if (tid < 10){
        float o = f2b[tid];
#pragma unroll 8
        for (int k = 0; k < 64; k++) o += hm[k] * f2w[k*10 + tid];
        out[g*10 + tid] = o;
    }
}

// ---------------- launch ----------------
extern "C" void kernel_launch(void* const* d_in, const int* in_sizes, int n_in,
                              void* d_out, int out_size){
    const float* x     = (const float*)d_in[0];
    const int*   ei    = (const int*)d_in[1];
    const int*   batch = (const int*)d_in[2];
    const float* W    = (const float*)d_in[3];
    const float* attS = (const float*)d_in[4];
    const float* attD = (const float*)d_in[5];
    const float* bias = (const float*)d_in[6];
    const float* gam  = (const float*)d_in[7];
    const float* bet  = (const float*)d_in[8];
    const float* mea  = (const float*)d_in[9];
    const float* var  = (const float*)d_in[10];
    const float* f1w  = (const float*)d_in[11];
    const float* f1b  = (const float*)d_in[12];
    const float* f2w  = (const float*)d_in[13];
    const float* f2b  = (const float*)d_in[14];
    float* out = (float*)d_out;

    const int smem_bytes = 2 * 128 * WSTRIDE * 2;   // 69632
    cudaFuncSetAttribute(gemm_mma_kernel, cudaFuncAttributeMaxDynamicSharedMemorySize, smem_bytes);

    const int gemm_blocks = (NN + 127) / 128;   // 391
    const int agg_blocks  = (NN + 7) / 8;

    wconv_zero_kernel<<<(NN + 255)/256, 256>>>(W);       // covers zero (NN) + wconv (49152)
    count_deg_kernel <<<(NET + 255)/256, 256>>>(ei);
    gemm_mma_kernel  <<<gemm_blocks, 256, smem_bytes>>>(0, 1, x, attS,             attD);
    scan1_kernel     <<<NBLK_SCAN, 1024>>>();
    scan3_kernel     <<<(NN + 255)/256, 256>>>();
    scatter_kernel   <<<(NET + 255)/256, 256>>>(ei);
    agg_kernel       <<<agg_blocks, 256>>>(bias,         gam,         bet,         mea,         var,         0);
    gemm_mma_kernel  <<<gemm_blocks, 256, smem_bytes>>>(1, 0, x, attS + HEADS*32,  attD + HEADS*32);
    agg_kernel       <<<agg_blocks, 256>>>(bias + HID,   gam + HID,   bet + HID,   mea + HID,   var + HID,   0);
    gemm_mma_kernel  <<<gemm_blocks, 256, smem_bytes>>>(2, 0, x, attS + 2*HEADS*32, attD + 2*HEADS*32);
    agg_kernel       <<<agg_blocks, 256>>>(bias + 2*HID, gam + 2*HID, bet + 2*HID, mea + 2*HID, var + 2*HID, 1);

    pool_head_kernel<<<NG, 128>>>(batch, f1w, f1b, f2w, f2b, out);
}

// round 16
// speedup vs baseline: 1.6781x; 1.0552x over previous
#include <cuda_runtime.h>
#include <cuda_bf16.h>
#include <cuda_fp16.h>
#include <cstdint>

#define NN   50000
#define NE   800000
#define NET  850000     // NE + NN self loops
#define NG   256
#define HID  128
#define HEADS 4
#define FULLM 0xffffffffu
#define WSTRIDE 136      // padded smem row stride (bf16 elems) -> conflict-free
#define NBLK_SCAN ((NN + 1023) / 1024)   // 49

// ---------------- device scratch (no allocs allowed) ----------------
__device__ __half g_hh[NN*HID];         // post-GEMM features (fp16, for gather)
__device__ float g_x1[NN*HID];          // final layer output (fp32, for pool)
__device__ __nv_bfloat16 g_xh[NN*HID];  // layer input, bf16 hi
__device__ __nv_bfloat16 g_xl[NN*HID];  // layer input, bf16 lo
__device__ __nv_bfloat16 g_wth[3*HID*HID];  // W^T bf16 hi  [layer][n][k]
__device__ __nv_bfloat16 g_wtl[3*HID*HID];  // W^T bf16 lo
__device__ float g_as[NN*HEADS];
__device__ float g_ad[NN*HEADS];
__device__ int   g_deg[NN];
__device__ int   g_rowptr[NN+1];
__device__ int   g_pos[NN];
__device__ int   g_esrc[NET];
__device__ int   g_bsum[NBLK_SCAN];

// ---------------- helpers ----------------
__device__ __forceinline__ float lrelu(float v){ return v < 0.f ? 0.2f * v : v; }

__device__ __forceinline__ void mma16816(float* c, uint32_t a0, uint32_t a1, uint32_t a2, uint32_t a3,
                                         uint32_t b0, uint32_t b1){
    asm volatile("mma.sync.aligned.m16n8k16.row.col.f32.bf16.bf16.f32 "
        "{%0,%1,%2,%3}, {%4,%5,%6,%7}, {%8,%9}, {%0,%1,%2,%3};"
        : "+f"(c[0]), "+f"(c[1]), "+f"(c[2]), "+f"(c[3])
        : "r"(a0), "r"(a1), "r"(a2), "r"(a3), "r"(b0), "r"(b1));
}

// split a float2 into packed bf16 hi + lo words
__device__ __forceinline__ uint32_t split_bf16(float2 f, uint32_t& lo){
    __nv_bfloat16 h0 = __float2bfloat16(f.x), h1 = __float2bfloat16(f.y);
    __nv_bfloat162 H = __halves2bfloat162(h0, h1);
    __nv_bfloat162 L = __halves2bfloat162(__float2bfloat16(f.x - __bfloat162float(h0)),
                                          __float2bfloat16(f.y - __bfloat162float(h1)));
    lo = *(uint32_t*)&L;
    return *(uint32_t*)&H;
}

// ---------------- graph build + W conversion -------------------------------
// fused: zero g_deg (i < NN) and transpose/split W (i < 3*HID*HID)
__global__ void wconv_zero_kernel(const float* __restrict__ W){
    int t = blockIdx.x * blockDim.x + threadIdx.x;
    if (t < NN) g_deg[t] = 0;
    if (t < 3*HID*HID){
        int l = t / (HID*HID), r = t - l*(HID*HID);
        int n = r >> 7, k = r & 127;
        float v = W[l*HID*HID + k*HID + n];   // transpose: [l][n][k] = W[l][k][n]
        __nv_bfloat16 h = __float2bfloat16(v);
        g_wth[t] = h;
        g_wtl[t] = __float2bfloat16(v - __bfloat162float(h));
    }
}

__global__ void count_deg_kernel(const int* __restrict__ ei){
    int e = blockIdx.x * blockDim.x + threadIdx.x;
    if (e >= NET) return;
    int d = (e < NE) ? ei[NE + e] : (e - NE);
    atomicAdd(&g_deg[d], 1);
}

// per-block inclusive scan of g_deg -> g_rowptr[i+1] (local), block totals -> g_bsum
__global__ void scan1_kernel(){
    __shared__ int warp_sums[32];
    int tid = threadIdx.x, lane = tid & 31, wid = tid >> 5;
    int i = blockIdx.x * 1024 + tid;
    int v = (i < NN) ? g_deg[i] : 0;
    int xs = v;
#pragma unroll
    for (int o = 1; o < 32; o <<= 1){
        int t = __shfl_up_sync(FULLM, xs, o);
        if (lane >= o) xs += t;
    }
    if (lane == 31) warp_sums[wid] = xs;
    __syncthreads();
    if (wid == 0){
        int y = warp_sums[lane];
#pragma unroll
        for (int o = 1; o < 32; o <<= 1){
            int t = __shfl_up_sync(FULLM, y, o);
            if (lane >= o) y += t;
        }
        warp_sums[lane] = y;
    }
    __syncthreads();
    int add = (wid > 0 ? warp_sums[wid-1] : 0);
    if (i < NN) g_rowptr[i+1] = xs + add;
    if (tid == 1023) g_bsum[blockIdx.x] = xs + add;
}

// adds block-prefix (computed redundantly per block: <=49 independent loads)
// and emits final rowptr + scatter cursor. 256 | 1024 so each block spans
// exactly one scan-block (sb = blockIdx.x >> 2).
__global__ void scan3_kernel(){
    __shared__ int carry_s;
    if (threadIdx.x == 0){
        int sb = blockIdx.x >> 2;
        int run = 0;
        for (int b = 0; b < sb; b++) run += g_bsum[b];
        carry_s = run;
    }
    __syncthreads();
    int carry = carry_s;
    int i = blockIdx.x * blockDim.x + threadIdx.x;
    if (i == 0) g_rowptr[0] = 0;
    if (i < NN){
        int r = g_rowptr[i+1] + carry;
        g_rowptr[i+1] = r;
        g_pos[i] = r - g_deg[i];
    }
}

__global__ void scatter_kernel(const int* __restrict__ ei){
    int e = blockIdx.x * blockDim.x + threadIdx.x;
    if (e >= NET) return;
    int s, d;
    if (e < NE){ s = ei[e]; d = ei[NE + e]; }
    else       { s = e - NE; d = e - NE; }
    int idx = atomicAdd(&g_pos[d], 1);
    g_esrc[idx] = s;
}

// ---------------- tensor-core GEMM h = x*W (+ fused alpha projections) --------
// CTA = 256 thr = 8 warps as 4 Mgroups x 2 Ngroups. Warp tile: M=32 (2 mtiles), N=64 (8 nt).
// 3-phase split-bf16: Ah*Bh + Al*Bh + Ah*Bl (proven 2.7e-5 logits error).
__global__ void __launch_bounds__(256, 2) gemm_mma_kernel(int layer, int srcF32,
        const float* __restrict__ xin,
        const float* __restrict__ attS, const float* __restrict__ attD){
    extern __shared__ __nv_bfloat16 ws[];          // [2][128][WSTRIDE]
    __nv_bfloat16* wh_s = ws;
    __nv_bfloat16* wl_s = ws + 128*WSTRIDE;

    int tid = threadIdx.x, lane = tid & 31, wid = tid >> 5;
    int Mg = wid >> 1, Ng = wid & 1;

    // stage W^T hi/lo into smem (row = n, 128 rows x 128 bf16 each)
    {
        const uint4* src_h = (const uint4*)&g_wth[(size_t)layer*HID*HID];
        const uint4* src_l = (const uint4*)&g_wtl[(size_t)layer*HID*HID];
        for (int i = tid; i < 2048; i += 256){     // 2048 uint4 per matrix
            int row = i >> 4, c16 = i & 15;
            *(uint4*)((char*)wh_s + row*(WSTRIDE*2) + c16*16) = src_h[i];
            *(uint4*)((char*)wl_s + row*(WSTRIDE*2) + c16*16) = src_l[i];
        }
    }
    __syncthreads();

    int rowBase = blockIdx.x * 128 + Mg * 32;
    int rq = lane >> 2;            // 0..7
    int kcol = (lane & 3) * 2;

    float acc[64];                 // [mt 2][nt 8][frag 4]
#pragma unroll
    for (int i = 0; i < 64; i++) acc[i] = 0.f;

#pragma unroll
    for (int ks = 0; ks < 8; ks++){
        int k0 = ks * 16;
        uint32_t ah[2][4], al[2][4];
#pragma unroll
        for (int mt = 0; mt < 2; mt++){
            int r0 = min(rowBase + mt*16 + rq,     NN-1);
            int r8 = min(rowBase + mt*16 + rq + 8, NN-1);
            if (srcF32){
                float2 f00 = *(const float2*)&xin[(size_t)r0*HID + k0 + kcol];
                float2 f10 = *(const float2*)&xin[(size_t)r8*HID + k0 + kcol];
                float2 f01 = *(const float2*)&xin[(size_t)r0*HID + k0 + kcol + 8];
                float2 f11 = *(const float2*)&xin[(size_t)r8*HID + k0 + kcol + 8];
                ah[mt][0] = split_bf16(f00, al[mt][0]);
                ah[mt][1] = split_bf16(f10, al[mt][1]);
                ah[mt][2] = split_bf16(f01, al[mt][2]);
                ah[mt][3] = split_bf16(f11, al[mt][3]);
            } else {
                ah[mt][0] = *(const uint32_t*)&g_xh[(size_t)r0*HID + k0 + kcol];
                ah[mt][1] = *(const uint32_t*)&g_xh[(size_t)r8*HID + k0 + kcol];
                ah[mt][2] = *(const uint32_t*)&g_xh[(size_t)r0*HID + k0 + kcol + 8];
                ah[mt][3] = *(const uint32_t*)&g_xh[(size_t)r8*HID + k0 + kcol + 8];
                al[mt][0] = *(const uint32_t*)&g_xl[(size_t)r0*HID + k0 + kcol];
                al[mt][1] = *(const uint32_t*)&g_xl[(size_t)r8*HID + k0 + kcol];
                al[mt][2] = *(const uint32_t*)&g_xl[(size_t)r0*HID + k0 + kcol + 8];
                al[mt][3] = *(const uint32_t*)&g_xl[(size_t)r8*HID + k0 + kcol + 8];
            }
        }
#pragma unroll
        for (int nt = 0; nt < 8; nt++){
            int n = Ng*64 + nt*8 + rq;
            uint32_t bh0 = *(const uint32_t*)&wh_s[n*WSTRIDE + k0 + kcol];
            uint32_t bh1 = *(const uint32_t*)&wh_s[n*WSTRIDE + k0 + kcol + 8];
            uint32_t bl0 = *(const uint32_t*)&wl_s[n*WSTRIDE + k0 + kcol];
            uint32_t bl1 = *(const uint32_t*)&wl_s[n*WSTRIDE + k0 + kcol + 8];
#pragma unroll
            for (int mt = 0; mt < 2; mt++){
                float* a = &acc[(mt*8 + nt)*4];
                mma16816(a, ah[mt][0], ah[mt][1], ah[mt][2], ah[mt][3], bh0, bh1);
                mma16816(a, al[mt][0], al[mt][1], al[mt][2], al[mt][3], bh0, bh1);
                mma16816(a, ah[mt][0], ah[mt][1], ah[mt][2], ah[mt][3], bl0, bl1);
            }
        }
    }

    // epilogue: warp owns cols [Ng*64, Ng*64+64) = heads 2Ng and 2Ng+1.
#pragma unroll
    for (int mt = 0; mt < 2; mt++){
        int r0 = rowBase + mt*16 + rq;
        int r1 = r0 + 8;
        float s0[2] = {0,0}, d0[2] = {0,0}, s1[2] = {0,0}, d1[2] = {0,0};
#pragma unroll
        for (int nt = 0; nt < 8; nt++){
            int c = Ng*64 + nt*8 + (lane & 3)*2;
            int hh = nt >> 2;                       // head within warp (0/1)
            float aS0 = __ldg(&attS[c]), aS1 = __ldg(&attS[c+1]);
            float aD0 = __ldg(&attD[c]), aD1 = __ldg(&attD[c+1]);
            float* a = &acc[(mt*8 + nt)*4];
            s0[hh] += a[0]*aS0 + a[1]*aS1;  d0[hh] += a[0]*aD0 + a[1]*aD1;
            s1[hh] += a[2]*aS0 + a[3]*aS1;  d1[hh] += a[2]*aD0 + a[3]*aD1;
            if (r0 < NN) *(__half2*)&g_hh[(size_t)r0*HID + c] = __floats2half2_rn(a[0], a[1]);
            if (r1 < NN) *(__half2*)&g_hh[(size_t)r1*HID + c] = __floats2half2_rn(a[2], a[3]);
        }
#pragma unroll
        for (int hh = 0; hh < 2; hh++){
            s0[hh] += __shfl_xor_sync(FULLM, s0[hh], 1); s0[hh] += __shfl_xor_sync(FULLM, s0[hh], 2);
            d0[hh] += __shfl_xor_sync(FULLM, d0[hh], 1); d0[hh] += __shfl_xor_sync(FULLM, d0[hh], 2);
            s1[hh] += __shfl_xor_sync(FULLM, s1[hh], 1); s1[hh] += __shfl_xor_sync(FULLM, s1[hh], 2);
            d1[hh] += __shfl_xor_sync(FULLM, d1[hh], 1); d1[hh] += __shfl_xor_sync(FULLM, d1[hh], 2);
        }
        if ((lane & 3) == 0){
            if (r0 < NN){
#pragma unroll
                for (int hh = 0; hh < 2; hh++){ g_as[r0*4 + Ng*2 + hh] = s0[hh]; g_ad[r0*4 + Ng*2 + hh] = d0[hh]; }
            }
            if (r1 < NN){
#pragma unroll
                for (int hh = 0; hh < 2; hh++){ g_as[r1*4 + Ng*2 + hh] = s1[hh]; g_ad[r1*4 + Ng*2 + hh] = d1[hh]; }
            }
        }
    }
}

// ---------------- fused single-pass softmax-aggregation + bias/BN/ELU --------
// warp per dst node (round-8 proven variant). Chunks of 8 edges:
//   lane l preloads exp score for (edge base+(l&7), head l>>3) -> exp once per (edge,head);
//   inner loop per edge: 2 shfl + 1 LDG.64 + FFMAs.
// Store elision: final layer (writeF32=1) writes only g_x1; earlier layers only g_xh/g_xl.
__global__ void agg_kernel(const float* __restrict__ bias,
                           const float* __restrict__ gam,
                           const float* __restrict__ bet,
                           const float* __restrict__ mea,
                           const float* __restrict__ var,
                           int writeF32){
    int v = blockIdx.x * 8 + (threadIdx.x >> 5);
    if (v >= NN) return;
    int lane = threadIdx.x & 31;
    int head = lane >> 3;
    int esub = lane & 7;
    int srcBase = head << 3;          // lane & 24

    float adh = g_ad[v*4 + head];
    int begin = g_rowptr[v], end = g_rowptr[v+1];

    float4 acc = {0,0,0,0};
    float denom = 0.f;

    for (int base = begin; base < end; base += 8){
        int n = end - base; if (n > 8) n = 8;
        int eidx = base + esub; if (eidx >= end) eidx = end - 1;
        int sidx = g_esrc[eidx];
        float e = __expf(lrelu(__ldg(&g_as[sidx*4 + head]) + adh));
#pragma unroll
        for (int j = 0; j < 8; j++){
            if (j >= n) break;
            int s = __shfl_sync(FULLM, sidx, j);
            float ej = __shfl_sync(FULLM, e, srcBase + j);
            uint2 p = *(const uint2*)&g_hh[(size_t)s*HID + lane*4];
            float2 fa = __half22float2(*reinterpret_cast<__half2*>(&p.x));
            float2 fb = __half22float2(*reinterpret_cast<__half2*>(&p.y));
            denom += ej;
            acc.x += ej*fa.x; acc.y += ej*fa.y;
            acc.z += ej*fb.x; acc.w += ej*fb.y;
        }
    }
    float inv = 1.0f / denom;
    acc.x *= inv; acc.y *= inv; acc.z *= inv; acc.w *= inv;

    // epilogue: bias + BN + ELU
    int c = lane * 4;
    float4 bi = *(const float4*)&bias[c];
    float4 gg = *(const float4*)&gam[c];
    float4 bb = *(const float4*)&bet[c];
    float4 mm = *(const float4*)&mea[c];
    float4 vv = *(const float4*)&var[c];
    float4 r;
    r.x = (acc.x + bi.x - mm.x) * (gg.x * rsqrtf(vv.x + 1e-5f)) + bb.x;
    r.y = (acc.y + bi.y - mm.y) * (gg.y * rsqrtf(vv.y + 1e-5f)) + bb.y;
    r.z = (acc.z + bi.z - mm.z) * (gg.z * rsqrtf(vv.z + 1e-5f)) + bb.z;
    r.w = (acc.w + bi.w - mm.w) * (gg.w * rsqrtf(vv.w + 1e-5f)) + bb.w;
    r.x = r.x > 0.f ? r.x : (expf(r.x) - 1.f);
    r.y = r.y > 0.f ? r.y : (expf(r.y) - 1.f);
    r.z = r.z > 0.f ? r.z : (expf(r.z) - 1.f);
    r.w = r.w > 0.f ? r.w : (expf(r.w) - 1.f);

    if (writeF32){
        // final layer: only the pooling path consumes this
        *(float4*)&g_x1[(size_t)v*HID + c] = r;
    } else {
        // split-bf16 outputs for next layer's tensor GEMM
        uint32_t l0, l1;
        uint32_t h0w = split_bf16({r.x, r.y}, l0);
        uint32_t h1w = split_bf16({r.z, r.w}, l1);
        uint2 hw = {h0w, h1w}, lw = {l0, l1};
        *(uint2*)&g_xh[(size_t)v*HID + c] = hw;
        *(uint2*)&g_xl[(size_t)v*HID + c] = lw;
    }
}

// ---------------- fused pool + head (batch is sorted by graph) ---------------
__global__ void pool_head_kernel(const int* __restrict__ batch,
                                 const float* __restrict__ f1w, const float* __restrict__ f1b,
                                 const float* __restrict__ f2w, const float* __restrict__ f2b,
                                 float* __restrict__ out){
    __shared__ float meanv[HID];
    __shared__ float hm[64];
    int g = blockIdx.x, tid = threadIdx.x;   // 128 threads

    int lo = 0, hi = NN;
    while (lo < hi){ int mid = (lo + hi) >> 1; if (batch[mid] < g) lo = mid + 1; else hi = mid; }
    int start = lo;
    hi = NN;
    while (lo < hi){ int mid = (lo + hi) >> 1; if (batch[mid] < g + 1) lo = mid + 1; else hi = mid; }
    int end = lo;

    float s = 0.f;
    for (int n = start; n < end; n++) s += g_x1[(size_t)n*HID + tid];
    float cnt = fmaxf((float)(end - start), 1.0f);
    meanv[tid] = s / cnt;
    __syncthreads();
    if (tid < 64){
        float a = f1b[tid];
#pragma unroll 8
        for (int k = 0; k < HID; k++) a += meanv[k] * f1w[k*64 + tid];
        hm[tid] = fmaxf(a, 0.f);
    }
    __syncthreads();
    if (tid < 10){
        float o = f2b[tid];
#pragma unroll 8
        for (int k = 0; k < 64; k++) o += hm[k] * f2w[k*10 + tid];
        out[g*10 + tid] = o;
    }
}

// ---------------- launch ----------------
extern "C" void kernel_launch(void* const* d_in, const int* in_sizes, int n_in,
                              void* d_out, int out_size){
    const float* x     = (const float*)d_in[0];
    const int*   ei    = (const int*)d_in[1];
    const int*   batch = (const int*)d_in[2];
    const float* W    = (const float*)d_in[3];
    const float* attS = (const float*)d_in[4];
    const float* attD = (const float*)d_in[5];
    const float* bias = (const float*)d_in[6];
    const float* gam  = (const float*)d_in[7];
    const float* bet  = (const float*)d_in[8];
    const float* mea  = (const float*)d_in[9];
    const float* var  = (const float*)d_in[10];
    const float* f1w  = (const float*)d_in[11];
    const float* f1b  = (const float*)d_in[12];
    const float* f2w  = (const float*)d_in[13];
    const float* f2b  = (const float*)d_in[14];
    float* out = (float*)d_out;

    const int smem_bytes = 2 * 128 * WSTRIDE * 2;   // 69632
    cudaFuncSetAttribute(gemm_mma_kernel, cudaFuncAttributeMaxDynamicSharedMemorySize, smem_bytes);

    const int gemm_blocks = (NN + 127) / 128;   // 391
    const int agg_blocks  = (NN + 7) / 8;

    // fork/join: graph build runs on a side stream, overlapped with gemm0.
    // Streams/events are created at capture time only (host-side, no device
    // allocation); the captured graph encodes the dependency structure.
    cudaStream_t s2;
    cudaEvent_t evFork, evJoin;
    cudaStreamCreateWithFlags(&s2, cudaStreamNonBlocking);
    cudaEventCreateWithFlags(&evFork, cudaEventDisableTiming);
    cudaEventCreateWithFlags(&evJoin, cudaEventDisableTiming);

    // main stream: W conversion + deg zero (both sides depend on this)
    wconv_zero_kernel<<<(NN + 255)/256, 256>>>(W);
    cudaEventRecord(evFork, 0);

    // side stream: CSR build chain
    cudaStreamWaitEvent(s2, evFork, 0);
    count_deg_kernel <<<(NET + 255)/256, 256, 0, s2>>>(ei);
    scan1_kernel     <<<NBLK_SCAN, 1024, 0, s2>>>();
    scan3_kernel     <<<(NN + 255)/256, 256, 0, s2>>>();
    scatter_kernel   <<<(NET + 255)/256, 256, 0, s2>>>(ei);
    cudaEventRecord(evJoin, s2);

    // main stream: layer-0 GEMM (independent of the build)
    gemm_mma_kernel  <<<gemm_blocks, 256, smem_bytes>>>(0, 1, x, attS, attD);

    // join before first aggregation
    cudaStreamWaitEvent(0, evJoin, 0);

    agg_kernel       <<<agg_blocks, 256>>>(bias,         gam,         bet,         mea,         var,         0);
    gemm_mma_kernel  <<<gemm_blocks, 256, smem_bytes>>>(1, 0, x, attS + HEADS*32,  attD + HEADS*32);
    agg_kernel       <<<agg_blocks, 256>>>(bias + HID,   gam + HID,   bet + HID,   mea + HID,   var + HID,   0);
    gemm_mma_kernel  <<<gemm_blocks, 256, smem_bytes>>>(2, 0, x, attS + 2*HEADS*32, attD + 2*HEADS*32);
    agg_kernel       <<<agg_blocks, 256>>>(bias + 2*HID, gam + 2*HID, bet + 2*HID, mea + 2*HID, var + 2*HID, 1);

    pool_head_kernel<<<NG, 128>>>(batch, f1w, f1b, f2w, f2b, out);
}